// round 1
// baseline (speedup 1.0000x reference)
#include <cuda_runtime.h>

// Problem constants
#define BATCH 32768
#define TT 21
#define FIN 126
#define UU 8
#define GG 32   // 4*units
#define NC 27

// Scratch: z1[b][t][g] = x_row . W1k + b1   (88 MB, __device__ global per alloc rules)
__device__ float g_z1[(size_t)BATCH * TT * GG];

// ---------------- packed f32x2 helpers (sm_100+ PTX) ----------------
__device__ __forceinline__ unsigned long long fma2(unsigned long long a,
                                                   unsigned long long b,
                                                   unsigned long long c) {
    unsigned long long d;
    asm("fma.rn.f32x2 %0, %1, %2, %3;" : "=l"(d) : "l"(a), "l"(b), "l"(c));
    return d;
}
__device__ __forceinline__ unsigned long long bcast2(float v) {
    unsigned long long d;
    asm("mov.b64 %0, {%1, %2};" : "=l"(d) : "f"(v), "f"(v));
    return d;
}
__device__ __forceinline__ unsigned long long pack2(float lo, float hi) {
    unsigned long long d;
    asm("mov.b64 %0, {%1, %2};" : "=l"(d) : "f"(lo), "f"(hi));
    return d;
}

// ---------------- Phase A: input projection ----------------
// x is (B, T*F) row-major == (B*T, F) row-major. Row r = b*T+t.
// Each thread computes 2 rows (amortizes the shared-W LDS against 2x FFMA2).
__global__ __launch_bounds__(256)
void input_proj_kernel(const float* __restrict__ x,
                       const float* __restrict__ W1k,
                       const float* __restrict__ b1) {
    __shared__ unsigned long long sW[FIN * 16];   // gate pairs, [f][g2]
    __shared__ unsigned long long sB[16];

    for (int i = threadIdx.x; i < FIN * 16; i += blockDim.x)
        sW[i] = pack2(W1k[2 * i], W1k[2 * i + 1]);   // 2*i == f*32 + 2*g2
    if (threadIdx.x < 16)
        sB[threadIdx.x] = pack2(b1[2 * threadIdx.x], b1[2 * threadIdx.x + 1]);
    __syncthreads();

    int tid = blockIdx.x * blockDim.x + threadIdx.x;
    size_t r0 = (size_t)2 * tid;
    size_t r1 = r0 + 1;

    const float2* x0 = (const float2*)(x + r0 * FIN);   // FIN even -> 8B aligned
    const float2* x1 = (const float2*)(x + r1 * FIN);

    unsigned long long a0[16], a1[16];
#pragma unroll
    for (int g = 0; g < 16; ++g) { a0[g] = sB[g]; a1[g] = sB[g]; }

#pragma unroll 3
    for (int f2 = 0; f2 < FIN / 2; ++f2) {
        float2 v0 = x0[f2];
        float2 v1 = x1[f2];
        unsigned long long b00 = bcast2(v0.x), b01 = bcast2(v0.y);
        unsigned long long b10 = bcast2(v1.x), b11 = bcast2(v1.y);
#pragma unroll
        for (int g = 0; g < 16; ++g) {
            unsigned long long wA = sW[(2 * f2) * 16 + g];
            unsigned long long wB = sW[(2 * f2 + 1) * 16 + g];
            a0[g] = fma2(b00, wA, a0[g]);
            a1[g] = fma2(b10, wA, a1[g]);
            a0[g] = fma2(b01, wB, a0[g]);
            a1[g] = fma2(b11, wB, a1[g]);
        }
    }

    // 16B stores
    ulonglong2* o0 = (ulonglong2*)(g_z1 + r0 * GG);
    ulonglong2* o1 = (ulonglong2*)(g_z1 + r1 * GG);
#pragma unroll
    for (int g = 0; g < 8; ++g) {
        o0[g] = make_ulonglong2(a0[2 * g], a0[2 * g + 1]);
        o1[g] = make_ulonglong2(a1[2 * g], a1[2 * g + 1]);
    }
}

// ---------------- Phase B: recurrent scan + dense + softmax ----------------
__device__ __forceinline__ float sigm(float v) {
    return 1.0f / (1.0f + expf(-v));
}

__global__ __launch_bounds__(256)
void recurrent_kernel(const float* __restrict__ W1r, const float* __restrict__ W2k,
                      const float* __restrict__ W2r, const float* __restrict__ b2,
                      const float* __restrict__ Wd, const float* __restrict__ bd,
                      float* __restrict__ out) {
    __shared__ float sW1r[UU * GG], sW2k[UU * GG], sW2r[UU * GG];
    __shared__ float sb2[GG], sWd[UU * NC], sbd[NC];

    for (int i = threadIdx.x; i < UU * GG; i += blockDim.x) {
        sW1r[i] = W1r[i]; sW2k[i] = W2k[i]; sW2r[i] = W2r[i];
    }
    for (int i = threadIdx.x; i < GG; i += blockDim.x) sb2[i] = b2[i];
    for (int i = threadIdx.x; i < UU * NC; i += blockDim.x) sWd[i] = Wd[i];
    for (int i = threadIdx.x; i < NC; i += blockDim.x) sbd[i] = bd[i];
    __syncthreads();

    int b = blockIdx.x * blockDim.x + threadIdx.x;

    float h1[UU], c1[UU], h2[UU], c2[UU];
#pragma unroll
    for (int k = 0; k < UU; ++k) { h1[k] = 0.f; c1[k] = 0.f; h2[k] = 0.f; c2[k] = 0.f; }

    const float4* zin = (const float4*)(g_z1 + (size_t)b * TT * GG);

    for (int t = 0; t < TT; ++t) {
        // ---- layer 1 ----
        float z[GG];
#pragma unroll
        for (int q = 0; q < 8; ++q) {
            float4 v = zin[t * 8 + q];
            z[4 * q] = v.x; z[4 * q + 1] = v.y; z[4 * q + 2] = v.z; z[4 * q + 3] = v.w;
        }
#pragma unroll
        for (int j = 0; j < UU; ++j) {
            float hj = h1[j];
#pragma unroll
            for (int g = 0; g < GG; ++g) z[g] += hj * sW1r[j * GG + g];
        }
#pragma unroll
        for (int k = 0; k < UU; ++k) {
            float ig = sigm(z[k]);
            float fg = sigm(z[8 + k]);
            float gg = tanhf(z[16 + k]);
            float og = sigm(z[24 + k]);
            c1[k] = fg * c1[k] + ig * gg;
            h1[k] = og * tanhf(c1[k]);
        }

        // ---- layer 2 ----
        float z2[GG];
#pragma unroll
        for (int g = 0; g < GG; ++g) z2[g] = sb2[g];
#pragma unroll
        for (int j = 0; j < UU; ++j) {
            float aj = h1[j];
            float bj = h2[j];
#pragma unroll
            for (int g = 0; g < GG; ++g)
                z2[g] += aj * sW2k[j * GG + g] + bj * sW2r[j * GG + g];
        }
#pragma unroll
        for (int k = 0; k < UU; ++k) {
            float ig = sigm(z2[k]);
            float fg = sigm(z2[8 + k]);
            float gg = tanhf(z2[16 + k]);
            float og = sigm(z2[24 + k]);
            c2[k] = fg * c2[k] + ig * gg;
            h2[k] = og * tanhf(c2[k]);
        }
    }

    // ---- dense + softmax ----
    float logit[NC];
#pragma unroll
    for (int k = 0; k < NC; ++k) logit[k] = sbd[k];
#pragma unroll
    for (int j = 0; j < UU; ++j) {
        float hj = h2[j];
#pragma unroll
        for (int k = 0; k < NC; ++k) logit[k] += hj * sWd[j * NC + k];
    }
    float m = logit[0];
#pragma unroll
    for (int k = 1; k < NC; ++k) m = fmaxf(m, logit[k]);
    float s = 0.f;
#pragma unroll
    for (int k = 0; k < NC; ++k) { logit[k] = expf(logit[k] - m); s += logit[k]; }
    float inv = 1.0f / s;
#pragma unroll
    for (int k = 0; k < NC; ++k) out[(size_t)b * NC + k] = logit[k] * inv;
}

// ---------------- launch ----------------
extern "C" void kernel_launch(void* const* d_in, const int* in_sizes, int n_in,
                              void* d_out, int out_size) {
    const float* x   = (const float*)d_in[0];
    const float* W1k = (const float*)d_in[1];
    const float* W1r = (const float*)d_in[2];
    const float* b1  = (const float*)d_in[3];
    const float* W2k = (const float*)d_in[4];
    const float* W2r = (const float*)d_in[5];
    const float* b2  = (const float*)d_in[6];
    const float* Wd  = (const float*)d_in[7];
    const float* bd  = (const float*)d_in[8];
    float* out = (float*)d_out;

    // Phase A: (B*T)/2 rows per thread-pair = 344064 threads
    input_proj_kernel<<<(BATCH * TT / 2) / 256, 256>>>(x, W1k, b1);
    // Phase B: one thread per batch element
    recurrent_kernel<<<BATCH / 256, 256>>>(W1r, W2k, W2r, b2, Wd, bd, out);
}

// round 2
// speedup vs baseline: 1.5362x; 1.5362x over previous
#include <cuda_runtime.h>

#define BATCH 32768
#define TT 21
#define FIN 126
#define UU 8
#define GG 32
#define NC 27

typedef unsigned long long ull;

// Scratch: permuted gate pre-activations z1[b][t][q][8]  (88 MB)
// Per (b,t), quad-lane q owns 8 floats: (i0,i1,f0,f1,g0,g1,o0,o1) for units 2q,2q+1.
__device__ float g_z1[(size_t)BATCH * TT * GG];

// ---------------- packed f32x2 helpers ----------------
__device__ __forceinline__ ull fma2(ull a, ull b, ull c) {
    ull d;
    asm("fma.rn.f32x2 %0, %1, %2, %3;" : "=l"(d) : "l"(a), "l"(b), "l"(c));
    return d;
}
__device__ __forceinline__ ull bcast2(float v) {
    ull d;
    asm("mov.b64 %0, {%1, %2};" : "=l"(d) : "f"(v), "f"(v));
    return d;
}
__device__ __forceinline__ ull pack2(float lo, float hi) {
    ull d;
    asm("mov.b64 %0, {%1, %2};" : "=l"(d) : "f"(lo), "f"(hi));
    return d;
}
__device__ __forceinline__ void unpack2(float& lo, float& hi, ull v) {
    asm("mov.b64 {%0, %1}, %2;" : "=f"(lo), "=f"(hi) : "l"(v));
}

// Fast activations: MUFU ex2 + rcp, rel err ~1e-6 (threshold 1e-3)
__device__ __forceinline__ float sigm(float x) {
    return __fdividef(1.0f, 1.0f + __expf(-x));
}
__device__ __forceinline__ float tanhg(float x) {
    return __fdividef(2.0f, 1.0f + __expf(-2.0f * x)) - 1.0f;
}

// ---------------- Phase A: input projection (B*T, FIN) @ (FIN, 32) ----------------
__global__ __launch_bounds__(256)
void input_proj_kernel(const float* __restrict__ x,
                       const float* __restrict__ W1k,
                       const float* __restrict__ b1) {
    __shared__ ull sW[FIN * 16];
    __shared__ ull sB[16];

    for (int i = threadIdx.x; i < FIN * 16; i += blockDim.x)
        sW[i] = pack2(W1k[2 * i], W1k[2 * i + 1]);
    if (threadIdx.x < 16)
        sB[threadIdx.x] = pack2(b1[2 * threadIdx.x], b1[2 * threadIdx.x + 1]);
    __syncthreads();

    int tid = blockIdx.x * blockDim.x + threadIdx.x;
    size_t r0 = (size_t)2 * tid;
    size_t r1 = r0 + 1;

    const float2* x0 = (const float2*)(x + r0 * FIN);
    const float2* x1 = (const float2*)(x + r1 * FIN);

    ull a0[16], a1[16];
#pragma unroll
    for (int g = 0; g < 16; ++g) { a0[g] = sB[g]; a1[g] = sB[g]; }

#pragma unroll 3
    for (int f2 = 0; f2 < FIN / 2; ++f2) {
        float2 v0 = x0[f2];
        float2 v1 = x1[f2];
        ull b00 = bcast2(v0.x), b01 = bcast2(v0.y);
        ull b10 = bcast2(v1.x), b11 = bcast2(v1.y);
#pragma unroll
        for (int g = 0; g < 16; ++g) {
            ull wA = sW[(2 * f2) * 16 + g];
            ull wB = sW[(2 * f2 + 1) * 16 + g];
            a0[g] = fma2(b00, wA, a0[g]);
            a1[g] = fma2(b10, wA, a1[g]);
            a0[g] = fma2(b01, wB, a0[g]);
            a1[g] = fma2(b11, wB, a1[g]);
        }
    }

    // Permuted stores: ULL slot (q*4+gi) = pair a[gi*4+q]  (gates gi*8+2q, gi*8+2q+1)
    ulonglong2* o0 = (ulonglong2*)(g_z1 + r0 * GG);
    ulonglong2* o1 = (ulonglong2*)(g_z1 + r1 * GG);
#pragma unroll
    for (int q = 0; q < 4; ++q) {
        o0[2 * q]     = make_ulonglong2(a0[q],     a0[4 + q]);
        o0[2 * q + 1] = make_ulonglong2(a0[8 + q], a0[12 + q]);
        o1[2 * q]     = make_ulonglong2(a1[q],     a1[4 + q]);
        o1[2 * q + 1] = make_ulonglong2(a1[8 + q], a1[12 + q]);
    }
}

// ---------------- Phase B: quad-cooperative recurrent scan ----------------
// 4 threads per batch element; thread q owns units {2q, 2q+1} of both layers.
__global__ __launch_bounds__(256)
void recurrent_kernel(const float* __restrict__ W1r, const float* __restrict__ W2k,
                      const float* __restrict__ W2r, const float* __restrict__ b2,
                      const float* __restrict__ Wd, const float* __restrict__ bd,
                      float* __restrict__ out) {
    // Packed layouts: sW1r float idx (j*4+q)*8 + 2*gi + s  = W1r[j][gi*8+2q+s]
    __shared__ __align__(16) float sW1r[8 * 32];       // 256
    __shared__ __align__(16) float sW2[8 * 64];        // 512: [j][q][ k<8: W2k | k>=8: W2r ]
    __shared__ __align__(16) float sb2s[32];
    __shared__ float sWd[UU * NC];
    __shared__ float sbd[NC];

    for (int i = threadIdx.x; i < 256; i += blockDim.x) {
        int j = i >> 5, q = (i >> 3) & 3, k = i & 7;
        sW1r[i] = W1r[j * 32 + (k >> 1) * 8 + 2 * q + (k & 1)];
    }
    for (int i = threadIdx.x; i < 512; i += blockDim.x) {
        int j = i >> 6, q = (i >> 4) & 3, k2 = i & 15;
        int k = k2 & 7;
        const float* src = (k2 < 8) ? W2k : W2r;
        sW2[i] = src[j * 32 + (k >> 1) * 8 + 2 * q + (k & 1)];
    }
    for (int i = threadIdx.x; i < 32; i += blockDim.x) {
        int q = i >> 3, k = i & 7;
        sb2s[i] = b2[(k >> 1) * 8 + 2 * q + (k & 1)];
    }
    for (int i = threadIdx.x; i < UU * NC; i += blockDim.x) sWd[i] = Wd[i];
    for (int i = threadIdx.x; i < NC; i += blockDim.x) sbd[i] = bd[i];
    __syncthreads();

    int gtid = blockIdx.x * blockDim.x + threadIdx.x;
    int e = gtid >> 2;            // batch element
    int q = threadIdx.x & 3;      // quad lane
    int qbase = threadIdx.x & 28; // quad base lane within warp

    const ull* w1u = (const ull*)sW1r + q * 4;      // [j*16 + gi]
    const ull* w2u = (const ull*)sW2 + q * 8;       // [j*32 + gi] / [j*32 + 4 + gi]
    const ull* b2u = (const ull*)sb2s + q * 4;

    float h1x0 = 0.f, h1x1 = 0.f, c1x0 = 0.f, c1x1 = 0.f;
    float h2x0 = 0.f, h2x1 = 0.f, c2x0 = 0.f, c2x1 = 0.f;

    const ulonglong2* zbase = (const ulonglong2*)(g_z1 + (size_t)e * TT * GG);

    for (int t = 0; t < TT; ++t) {
        // ---- layer 1 ----
        ulonglong2 p01 = zbase[t * 8 + q * 2];
        ulonglong2 p23 = zbase[t * 8 + q * 2 + 1];
        ull zi = p01.x, zf = p01.y, zg = p23.x, zo = p23.y;

#pragma unroll
        for (int j = 0; j < 8; ++j) {
            float hj = __shfl_sync(0xffffffffu,
                                   (j & 1) ? h1x1 : h1x0, qbase | (j >> 1));
            ull hb = bcast2(hj);
            zi = fma2(hb, w1u[j * 16 + 0], zi);
            zf = fma2(hb, w1u[j * 16 + 1], zf);
            zg = fma2(hb, w1u[j * 16 + 2], zg);
            zo = fma2(hb, w1u[j * 16 + 3], zo);
        }
        {
            float i0, i1, f0, f1, g0, g1, o0, o1;
            unpack2(i0, i1, zi); unpack2(f0, f1, zf);
            unpack2(g0, g1, zg); unpack2(o0, o1, zo);
            c1x0 = sigm(f0) * c1x0 + sigm(i0) * tanhg(g0);
            c1x1 = sigm(f1) * c1x1 + sigm(i1) * tanhg(g1);
            h1x0 = sigm(o0) * tanhg(c1x0);
            h1x1 = sigm(o1) * tanhg(c1x1);
        }

        // ---- layer 2 ----
        zi = b2u[0]; zf = b2u[1]; zg = b2u[2]; zo = b2u[3];
#pragma unroll
        for (int j = 0; j < 8; ++j) {
            float aj = __shfl_sync(0xffffffffu,
                                   (j & 1) ? h1x1 : h1x0, qbase | (j >> 1));
            float bj = __shfl_sync(0xffffffffu,
                                   (j & 1) ? h2x1 : h2x0, qbase | (j >> 1));
            ull ab = bcast2(aj), bb = bcast2(bj);
            zi = fma2(ab, w2u[j * 32 + 0], zi);
            zf = fma2(ab, w2u[j * 32 + 1], zf);
            zg = fma2(ab, w2u[j * 32 + 2], zg);
            zo = fma2(ab, w2u[j * 32 + 3], zo);
            zi = fma2(bb, w2u[j * 32 + 4], zi);
            zf = fma2(bb, w2u[j * 32 + 5], zf);
            zg = fma2(bb, w2u[j * 32 + 6], zg);
            zo = fma2(bb, w2u[j * 32 + 7], zo);
        }
        {
            float i0, i1, f0, f1, g0, g1, o0, o1;
            unpack2(i0, i1, zi); unpack2(f0, f1, zf);
            unpack2(g0, g1, zg); unpack2(o0, o1, zo);
            c2x0 = sigm(f0) * c2x0 + sigm(i0) * tanhg(g0);
            c2x1 = sigm(f1) * c2x1 + sigm(i1) * tanhg(g1);
            h2x0 = sigm(o0) * tanhg(c2x0);
            h2x1 = sigm(o1) * tanhg(c2x1);
        }
    }

    // ---- dense + softmax (gather h2, lane q==0 computes & writes) ----
    float h2f[8];
#pragma unroll
    for (int j = 0; j < 8; ++j)
        h2f[j] = __shfl_sync(0xffffffffu, (j & 1) ? h2x1 : h2x0, qbase | (j >> 1));

    if (q == 0) {
        float logit[NC];
#pragma unroll
        for (int k = 0; k < NC; ++k) logit[k] = sbd[k];
#pragma unroll
        for (int j = 0; j < 8; ++j) {
            float hj = h2f[j];
#pragma unroll
            for (int k = 0; k < NC; ++k) logit[k] += hj * sWd[j * NC + k];
        }
        float m = logit[0];
#pragma unroll
        for (int k = 1; k < NC; ++k) m = fmaxf(m, logit[k]);
        float s = 0.f;
#pragma unroll
        for (int k = 0; k < NC; ++k) { logit[k] = __expf(logit[k] - m); s += logit[k]; }
        float inv = __fdividef(1.0f, s);
        float* op = out + (size_t)e * NC;
#pragma unroll
        for (int k = 0; k < NC; ++k) op[k] = logit[k] * inv;
    }
}

// ---------------- launch ----------------
extern "C" void kernel_launch(void* const* d_in, const int* in_sizes, int n_in,
                              void* d_out, int out_size) {
    const float* x   = (const float*)d_in[0];
    const float* W1k = (const float*)d_in[1];
    const float* W1r = (const float*)d_in[2];
    const float* b1  = (const float*)d_in[3];
    const float* W2k = (const float*)d_in[4];
    const float* W2r = (const float*)d_in[5];
    const float* b2  = (const float*)d_in[6];
    const float* Wd  = (const float*)d_in[7];
    const float* bd  = (const float*)d_in[8];
    float* out = (float*)d_out;

    input_proj_kernel<<<(BATCH * TT / 2) / 256, 256>>>(x, W1k, b1);
    recurrent_kernel<<<(BATCH * 4) / 256, 256>>>(W1r, W2k, W2r, b2, Wd, bd, out);
}

// round 3
// speedup vs baseline: 2.8226x; 1.8374x over previous
#include <cuda_runtime.h>

#define BATCH 32768
#define TT 21
#define FIN 126
#define UU 8
#define GG 32
#define NC 27

typedef unsigned long long ull;

// Scratch: gate pre-activations, per (b,t): 8 units x float4(i,f,g,o)  (88 MB)
__device__ float g_z1[(size_t)BATCH * TT * GG];

// ---------------- packed f32x2 helpers ----------------
__device__ __forceinline__ ull fma2(ull a, ull b, ull c) {
    ull d;
    asm("fma.rn.f32x2 %0, %1, %2, %3;" : "=l"(d) : "l"(a), "l"(b), "l"(c));
    return d;
}
__device__ __forceinline__ ull bcast2(float v) {
    ull d;
    asm("mov.b64 %0, {%1, %2};" : "=l"(d) : "f"(v), "f"(v));
    return d;
}
__device__ __forceinline__ ull pack2(float lo, float hi) {
    ull d;
    asm("mov.b64 %0, {%1, %2};" : "=l"(d) : "f"(lo), "f"(hi));
    return d;
}
__device__ __forceinline__ void unpack2(float& lo, float& hi, ull v) {
    asm("mov.b64 {%0, %1}, %2;" : "=f"(lo), "=f"(hi) : "l"(v));
}

// Fast activations: MUFU-based, rel err ~1e-6 (threshold 1e-3)
__device__ __forceinline__ float sigm(float x) {
    return __fdividef(1.0f, 1.0f + __expf(-x));
}
__device__ __forceinline__ float tanhg(float x) {
    return __fdividef(2.0f, 1.0f + __expf(-2.0f * x)) - 1.0f;
}

// ---------------- Phase A: input projection (B*T,126) @ (126,32) ----------------
__global__ __launch_bounds__(256)
void input_proj_kernel(const float* __restrict__ x,
                       const float* __restrict__ W1k,
                       const float* __restrict__ b1) {
    // Weight pairs as ulonglong2: sWp[f*8+g2] = pairs (4g2,4g2+1),(4g2+2,4g2+3) of column f
    __shared__ __align__(16) ulonglong2 sWp[FIN * 8];
    __shared__ ull sB[16];

    for (int i = threadIdx.x; i < FIN * 8; i += blockDim.x) {
        int f = i >> 3, g2 = i & 7;
        const float* w = W1k + f * GG + 4 * g2;
        sWp[i] = make_ulonglong2(pack2(w[0], w[1]), pack2(w[2], w[3]));
    }
    if (threadIdx.x < 16)
        sB[threadIdx.x] = pack2(b1[2 * threadIdx.x], b1[2 * threadIdx.x + 1]);
    __syncthreads();

    int tid = blockIdx.x * blockDim.x + threadIdx.x;
    size_t r0 = (size_t)2 * tid;
    size_t r1 = r0 + 1;

    const float2* x0 = (const float2*)(x + r0 * FIN);
    const float2* x1 = (const float2*)(x + r1 * FIN);

    ull a0[16], a1[16];
#pragma unroll
    for (int g = 0; g < 16; ++g) { a0[g] = sB[g]; a1[g] = sB[g]; }

#pragma unroll 7
    for (int f2 = 0; f2 < FIN / 2; ++f2) {
        float2 v0 = x0[f2];
        float2 v1 = x1[f2];
        ull b00 = bcast2(v0.x), b01 = bcast2(v0.y);
        ull b10 = bcast2(v1.x), b11 = bcast2(v1.y);
#pragma unroll
        for (int g2 = 0; g2 < 8; ++g2) {
            ulonglong2 wA = sWp[(2 * f2) * 8 + g2];
            ulonglong2 wB = sWp[(2 * f2 + 1) * 8 + g2];
            a0[2 * g2]     = fma2(b00, wA.x, a0[2 * g2]);
            a0[2 * g2 + 1] = fma2(b00, wA.y, a0[2 * g2 + 1]);
            a1[2 * g2]     = fma2(b10, wA.x, a1[2 * g2]);
            a1[2 * g2 + 1] = fma2(b10, wA.y, a1[2 * g2 + 1]);
            a0[2 * g2]     = fma2(b01, wB.x, a0[2 * g2]);
            a0[2 * g2 + 1] = fma2(b01, wB.y, a0[2 * g2 + 1]);
            a1[2 * g2]     = fma2(b11, wB.x, a1[2 * g2]);
            a1[2 * g2 + 1] = fma2(b11, wB.y, a1[2 * g2 + 1]);
        }
    }

    // Epilogue: unpack, store per-unit float4 (i_k, f_k, g_k, o_k)
    float ga0[GG], ga1[GG];
#pragma unroll
    for (int g = 0; g < 16; ++g) {
        unpack2(ga0[2 * g], ga0[2 * g + 1], a0[g]);
        unpack2(ga1[2 * g], ga1[2 * g + 1], a1[g]);
    }
    float4* o0 = (float4*)(g_z1 + r0 * GG);
    float4* o1 = (float4*)(g_z1 + r1 * GG);
#pragma unroll
    for (int k = 0; k < 8; ++k) {
        o0[k] = make_float4(ga0[k], ga0[8 + k], ga0[16 + k], ga0[24 + k]);
        o1[k] = make_float4(ga1[k], ga1[8 + k], ga1[16 + k], ga1[24 + k]);
    }
}

// ---------------- Phase B: octet-per-element, weights in registers ----------------
// 8 threads per batch element; thread k owns unit k of both layers.
// Gates packed as two f32x2 chains: (i,f) and (g,o).
__global__ __launch_bounds__(128)
void recurrent_kernel(const float* __restrict__ W1r, const float* __restrict__ W2k,
                      const float* __restrict__ W2r, const float* __restrict__ b2,
                      const float* __restrict__ Wd, const float* __restrict__ bd,
                      float* __restrict__ out) {
    int gtid = blockIdx.x * blockDim.x + threadIdx.x;
    int e = gtid >> 3;                 // batch element
    int lane = threadIdx.x & 31;
    int k = lane & 7;                  // unit
    int obase = lane & 24;             // octet base lane

    // Load weights into registers (once)
    ull w1if[8], w1go[8], w2kif[8], w2kgo[8], w2rif[8], w2rgo[8];
#pragma unroll
    for (int j = 0; j < 8; ++j) {
        const float* r1 = W1r + j * GG;
        const float* k2 = W2k + j * GG;
        const float* r2 = W2r + j * GG;
        w1if[j]  = pack2(r1[k], r1[8 + k]);
        w1go[j]  = pack2(r1[16 + k], r1[24 + k]);
        w2kif[j] = pack2(k2[k], k2[8 + k]);
        w2kgo[j] = pack2(k2[16 + k], k2[24 + k]);
        w2rif[j] = pack2(r2[k], r2[8 + k]);
        w2rgo[j] = pack2(r2[16 + k], r2[24 + k]);
    }
    ull b2if = pack2(b2[k], b2[8 + k]);
    ull b2go = pack2(b2[16 + k], b2[24 + k]);

    float h1 = 0.f, c1 = 0.f, h2 = 0.f, c2 = 0.f;
    const ulonglong2* zbase = (const ulonglong2*)(g_z1 + (size_t)e * TT * GG) + k;

    for (int t = 0; t < TT; ++t) {
        // ---- layer 1 ----
        ulonglong2 zz = zbase[t * 8];
        ull zif = zz.x, zgo = zz.y;
#pragma unroll
        for (int j = 0; j < 8; ++j) {
            float hj = __shfl_sync(0xffffffffu, h1, obase | j);
            ull hb = bcast2(hj);
            zif = fma2(hb, w1if[j], zif);
            zgo = fma2(hb, w1go[j], zgo);
        }
        {
            float zi, zf, zg, zo;
            unpack2(zi, zf, zif);
            unpack2(zg, zo, zgo);
            c1 = sigm(zf) * c1 + sigm(zi) * tanhg(zg);
            h1 = sigm(zo) * tanhg(c1);
        }

        // ---- layer 2 ----
        zif = b2if; zgo = b2go;
#pragma unroll
        for (int j = 0; j < 8; ++j) {
            float aj = __shfl_sync(0xffffffffu, h1, obase | j);
            float bj = __shfl_sync(0xffffffffu, h2, obase | j);
            ull ab = bcast2(aj), bb = bcast2(bj);
            zif = fma2(ab, w2kif[j], zif);
            zgo = fma2(ab, w2kgo[j], zgo);
            zif = fma2(bb, w2rif[j], zif);
            zgo = fma2(bb, w2rgo[j], zgo);
        }
        {
            float zi, zf, zg, zo;
            unpack2(zi, zf, zif);
            unpack2(zg, zo, zgo);
            c2 = sigm(zf) * c2 + sigm(zi) * tanhg(zg);
            h2 = sigm(zo) * tanhg(c2);
        }
    }

    // ---- dense + softmax, distributed over octet ----
    float h2f[8];
#pragma unroll
    for (int j = 0; j < 8; ++j)
        h2f[j] = __shfl_sync(0xffffffffu, h2, obase | j);

    // lane k computes logits m = k, 8+k, 16+k, 24+k (last only if < 27)
    float lg[4];
    int nm = (k < 3) ? 4 : 3;
#pragma unroll
    for (int q = 0; q < 4; ++q) {
        int m = q * 8 + k;
        float acc = (m < NC) ? bd[m] : -1e30f;
        if (m < NC) {
#pragma unroll
            for (int j = 0; j < 8; ++j) acc += h2f[j] * Wd[j * NC + m];
        }
        lg[q] = acc;
    }
    float mx = fmaxf(fmaxf(lg[0], lg[1]), fmaxf(lg[2], lg[3]));
#pragma unroll
    for (int off = 4; off >= 1; off >>= 1)
        mx = fmaxf(mx, __shfl_xor_sync(0xffffffffu, mx, off));
    float s = 0.f;
#pragma unroll
    for (int q = 0; q < 4; ++q) {
        float v = (q * 8 + k < NC) ? __expf(lg[q] - mx) : 0.f;
        lg[q] = v;
        s += v;
    }
#pragma unroll
    for (int off = 4; off >= 1; off >>= 1)
        s += __shfl_xor_sync(0xffffffffu, s, off);
    float inv = __fdividef(1.0f, s);
    float* op = out + (size_t)e * NC;
#pragma unroll
    for (int q = 0; q < 4; ++q) {
        int m = q * 8 + k;
        if (m < NC) op[m] = lg[q] * inv;
    }
}

// ---------------- launch ----------------
extern "C" void kernel_launch(void* const* d_in, const int* in_sizes, int n_in,
                              void* d_out, int out_size) {
    const float* x   = (const float*)d_in[0];
    const float* W1k = (const float*)d_in[1];
    const float* W1r = (const float*)d_in[2];
    const float* b1  = (const float*)d_in[3];
    const float* W2k = (const float*)d_in[4];
    const float* W2r = (const float*)d_in[5];
    const float* b2  = (const float*)d_in[6];
    const float* Wd  = (const float*)d_in[7];
    const float* bd  = (const float*)d_in[8];
    float* out = (float*)d_out;

    input_proj_kernel<<<(BATCH * TT / 2) / 256, 256>>>(x, W1k, b1);
    recurrent_kernel<<<(BATCH * 8) / 128, 128>>>(W1r, W2k, W2r, b2, Wd, bd, out);
}